// round 16
// baseline (speedup 1.0000x reference)
#include <cuda_runtime.h>
#include <cuda_fp16.h>
#include <math.h>
#include <stdint.h>

#define SEQ   4096
#define HID   2048
#define NHQ   32
#define NHKV  4
#define DH    128
#define DQTOT (NHQ*DH)
#define DKVTOT (NHKV*DH)

// ---------------- scratch ----------------
__device__ uint4 g_XhQ [(HID/16) * (SEQ/16) * 32];   // X fp16 a-frag quads, 16MB
__device__ uint2 g_WqB[(HID/16) * DQTOT * 4];        // Wq fp16 b-frag pairs, 16MB
__device__ uint2 g_WkB[(HID/16) * DKVTOT * 4];       // 2MB
__device__ uint2 g_WvB[(HID/16) * DKVTOT * 4];       // 2MB
__device__ uint2 g_WoB[(DQTOT/16) * HID * 4];        // 16MB
__device__ uint32_t g_Qh[SEQ * DQTOT / 2];           // Q fp16 pairs row-major, 32MB
__device__ uint2 g_KP2[NHKV * 8 * SEQ * 4];          // K fp16 b-frag layout, 4MB
__device__ uint2 g_VP[NHKV * DH * (SEQ/16) * 4];     // V fp16 pair layout, 4MB
__device__ uint4 g_OQ[(DQTOT/16) * (SEQ/16) * 32];   // O fp16 a-frag quads, 32MB

// ---------------- helpers ----------------
__device__ __forceinline__ uint32_t h2pack(float a, float b) {
    __half2 h = __floats2half2_rn(a, b);
    return *(uint32_t*)&h;
}
__device__ __forceinline__ void mma16h(float* c, const uint32_t* a, const uint32_t* b) {
    asm volatile("mma.sync.aligned.m16n8k16.row.col.f32.f16.f16.f32 "
        "{%0,%1,%2,%3}, {%4,%5,%6,%7}, {%8,%9}, {%0,%1,%2,%3};\n"
        : "+f"(c[0]), "+f"(c[1]), "+f"(c[2]), "+f"(c[3])
        : "r"(a[0]), "r"(a[1]), "r"(a[2]), "r"(a[3]), "r"(b[0]), "r"(b[1]));
}
__device__ __forceinline__ void cp16(uint32_t dst, const void* src) {
    asm volatile("cp.async.ca.shared.global [%0], [%1], 16;\n" :: "r"(dst), "l"(src));
}
__device__ __forceinline__ void cp_commit() { asm volatile("cp.async.commit_group;\n"); }
__device__ __forceinline__ void cp_wait0()  { asm volatile("cp.async.wait_group 0;\n"); }
__device__ __forceinline__ void cp_wait1()  { asm volatile("cp.async.wait_group 1;\n"); }

// ---------------- prep kernels ----------------
__global__ void prep_XQh(const float* __restrict__ X, uint4* __restrict__ XhQ)
{
    int id  = blockIdx.x * 256 + threadIdx.x;
    int tig = id & 3, gid = (id >> 2) & 7, rg = (id >> 5) & (SEQ/16 - 1), c = id >> 13;
    const float* p0 = X + (size_t)(rg * 16 + gid) * HID + c * 16 + 2 * tig;
    const float* p1 = p0 + (size_t)8 * HID;
    float2 a0 = *(const float2*)p0, a1 = *(const float2*)p1;
    float2 a2 = *(const float2*)(p0 + 8), a3 = *(const float2*)(p1 + 8);
    XhQ[id] = make_uint4(h2pack(a0.x, a0.y), h2pack(a1.x, a1.y),
                         h2pack(a2.x, a2.y), h2pack(a3.x, a3.y));
}
__global__ void prep_W2(const float* __restrict__ W, uint2* __restrict__ out,
                        int N, int nMask, int nShift)
{
    int id = blockIdx.x * 256 + threadIdx.x;
    int tg = id & 3, n = (id >> 2) & nMask, c = id >> (2 + nShift);
    const float* Wp = W + (size_t)(16 * c + 2 * tg) * N + n;
    out[id] = make_uint2(h2pack(Wp[0],           Wp[(size_t)N]),
                         h2pack(Wp[(size_t)8*N], Wp[(size_t)9*N]));
}

// ===========================================================================
// gemm_f16q<EPI>: fp16 single-pass GEMM (unchanged from R14).
// EPI=0: f32 C (Wo). 1: RoPE-Q -> Qh. 2: RoPE-K -> KP2. 3: V pack -> VP.
// ===========================================================================
#define F16Q_SMEM_BYTES 67584

template<int EPI>
__global__ __launch_bounds__(256, 2) void gemm_f16q(
    const uint4* __restrict__ AQ, const uint2* __restrict__ B2,
    const int* __restrict__ pos, float* __restrict__ C,
    uint2* __restrict__ VP, uint32_t* __restrict__ Qh, uint2* __restrict__ KP2,
    int M, int N, int K)
{
    extern __shared__ uint32_t smq[];
    const uint32_t smBase = (uint32_t)__cvta_generic_to_shared(smq);
    const int tid = threadIdx.x, lane = tid & 31, w = tid >> 5;
    const int wm = w >> 2, wn = w & 3;
    const int m0 = blockIdx.y * 128, n0 = blockIdx.x * 128;
    const int hb = blockIdx.x;
    const int gid = lane >> 2, tig = lane & 3;
    const int Mg = M >> 4, rg0 = m0 >> 4;

    float c[4][4][4];
#pragma unroll
    for (int mt = 0; mt < 4; mt++)
#pragma unroll
        for (int nt = 0; nt < 4; nt++)
#pragma unroll
            for (int q = 0; q < 4; q++) c[mt][nt][q] = 0.f;

#define F16Q_LOAD(t, buf) do {                                                 \
    _Pragma("unroll")                                                          \
    for (int l = 0; l < 2; l++) {                                              \
        int task = tid + l * 256;                                              \
        int ck = task >> 8, rg = (task >> 5) & 7, ln = task & 31;              \
        cp16(smBase + ((buf) * 512 + ck * 256 + rg * 32 + ln) * 16,            \
             AQ + ((size_t)((t) * 2 + ck) * Mg + rg0 + rg) * 32 + ln);         \
    }                                                                          \
    _Pragma("unroll")                                                          \
    for (int l = 0; l < 2; l++) {                                              \
        int task = tid + l * 256;                                              \
        int ck = task >> 8, n = (task >> 1) & 127, hf = task & 1;              \
        cp16(smBase + 16384 + ((buf) * 1024 + (ck * 128 + n) * 4 + hf * 2) * 8,\
             B2 + ((size_t)((t) * 2 + ck) * N + n0 + n) * 4 + hf * 2);         \
    }                                                                          \
    cp_commit();                                                               \
} while (0)

    const uint4* AQS = (const uint4*)smq;
    const uint2* B2S = (const uint2*)(smq + 4096);
    const int NT = K / 32;
    F16Q_LOAD(0, 0);
    for (int t = 0; t < NT; t++) {
        cp_wait0();
        __syncthreads();
        if (t + 1 < NT) F16Q_LOAD(t + 1, (t + 1) & 1);
        const int buf = t & 1;
#pragma unroll
        for (int ck = 0; ck < 2; ck++) {
            uint32_t a[4][4];
#pragma unroll
            for (int mt = 0; mt < 4; mt++) {
                uint4 va = AQS[buf * 512 + ck * 256 + (wm * 4 + mt) * 32 + lane];
                a[mt][0] = va.x; a[mt][1] = va.y; a[mt][2] = va.z; a[mt][3] = va.w;
            }
#pragma unroll
            for (int nt = 0; nt < 4; nt++) {
                int nc = wn * 32 + nt * 8 + gid;
                uint2 bu = B2S[buf * 1024 + ck * 512 + nc * 4 + tig];
                uint32_t b[2] = { bu.x, bu.y };
#pragma unroll
                for (int mt = 0; mt < 4; mt++)
                    mma16h(c[mt][nt], a[mt], b);
            }
        }
    }

    if (EPI == 0) {
#pragma unroll
        for (int mt = 0; mt < 4; mt++)
#pragma unroll
            for (int nt = 0; nt < 4; nt++) {
                int row = m0 + wm * 64 + mt * 16 + gid;
                int col = n0 + wn * 32 + nt * 8 + 2 * tig;
                *(float2*)&C[(size_t)row * N + col] = make_float2(c[mt][nt][0], c[mt][nt][1]);
                *(float2*)&C[(size_t)(row + 8) * N + col] = make_float2(c[mt][nt][2], c[mt][nt][3]);
            }
        return;
    }
    if (EPI == 3) {
        __syncthreads();
        uint32_t* stg = smq;
#pragma unroll
        for (int mt = 0; mt < 4; mt++)
#pragma unroll
            for (int nt = 0; nt < 4; nt++) {
                int rm = wm * 64 + mt * 16 + gid;
                int cu = wn * 16 + nt * 4 + tig;
                stg[rm * 66 + cu]       = h2pack(c[mt][nt][0], c[mt][nt][1]);
                stg[(rm + 8) * 66 + cu] = h2pack(c[mt][nt][2], c[mt][nt][3]);
            }
        __syncthreads();
        const __half* sh = (const __half*)smq;
        int hk = n0 >> 7, jg0 = m0 >> 4;
#pragma unroll
        for (int i = 0; i < 16; i++) {
            int task = tid + i * 256;
            int d = task >> 5, jl = (task >> 2) & 7, tg = task & 3;
            int s = 16 * jl + 2 * tg;
            __half2 pA = __halves2half2(sh[s * 132 + d],       sh[(s + 1) * 132 + d]);
            __half2 pB = __halves2half2(sh[(s + 8) * 132 + d], sh[(s + 9) * 132 + d]);
            VP[((size_t)(hk * 128 + d) * 256 + jg0 + jl) * 4 + tg] =
                make_uint2(*(uint32_t*)&pA, *(uint32_t*)&pB);
        }
        return;
    }
    __syncthreads();
    float* stage = (float*)smq;   // [128][132]
#pragma unroll
    for (int mt = 0; mt < 4; mt++)
#pragma unroll
        for (int nt = 0; nt < 4; nt++) {
            int row = wm * 64 + mt * 16 + gid;
            int col = wn * 32 + nt * 8 + 2 * tig;
            *(float2*)&stage[row * 132 + col] = make_float2(c[mt][nt][0], c[mt][nt][1]);
            *(float2*)&stage[(row + 8) * 132 + col] = make_float2(c[mt][nt][2], c[mt][nt][3]);
        }
    __syncthreads();
    {
        const int j  = tid & 31;
        const int rb = tid >> 5;
        const float inv0 = powf(10000.0f, -(float)(2 * j)     / 64.0f);
        const float inv1 = powf(10000.0f, -(float)(2 * j + 1) / 64.0f);
        const float SC = (EPI == 1) ? 0.08838834764831845f : 1.0f;
        const int cL = j >> 3, tg = j & 3, slot = (j >> 2) & 1;
#pragma unroll 4
        for (int i = 0; i < 16; i++) {
            int r = rb + i * 8;
            int s = m0 + r;
            float p = (float)pos[s];
            float s0, c0, s1, c1;
            sincosf(p * inv0, &s0, &c0);
            sincosf(p * inv1, &s1, &c1);
            float xL0 = stage[r * 132 + 2 * j],      xL1 = stage[r * 132 + 2 * j + 1];
            float xH0 = stage[r * 132 + 2 * j + 64], xH1 = stage[r * 132 + 2 * j + 65];
            float oL0 = (xL0 * c0 - xH0 * s0) * SC;
            float oL1 = (xL1 * c1 - xH1 * s1) * SC;
            float oH0 = (xH0 * c0 + xL0 * s0) * SC;
            float oH1 = (xH1 * c1 + xL1 * s1) * SC;
            if (EPI == 1) {
                size_t base = (size_t)s * 2048 + hb * 64;
                Qh[base + j]      = h2pack(oL0, oL1);
                Qh[base + 32 + j] = h2pack(oH0, oH1);
            } else {
                ((uint32_t*)&KP2[((size_t)(hb * 8 + cL) * SEQ + s) * 4 + tg])[slot] =
                    h2pack(oL0, oL1);
                ((uint32_t*)&KP2[((size_t)(hb * 8 + 4 + cL) * SEQ + s) * 4 + tg])[slot] =
                    h2pack(oH0, oH1);
            }
        }
    }
}

// ===========================================================================
// flash_mma v2: 128 q-rows x 64 kv tiles. 8 warps = 4(m, 32 rows) x 2(n).
// QK: warp 32 rows x 32 kv cols (each K frag -> 2 mma). P exchanged via smem
// (pitch-36, conflict-free). PV: warp 32 rows x 64 d cols (each V frag -> 2
// mma). l = per-warp partial sums, combined once at the end (no-max softmax).
// smem u32: K uint2[2][2048] @0, V uint2[2][2560] @8192, P[128][36] @18432,
// L2[256] @23040. Total 23296 u32 = 93184 B.
// ===========================================================================
#define FL_SMEM_BYTES (23296 * 4)

__global__ __launch_bounds__(256, 1) void flash_mma(
    const uint32_t* __restrict__ Qh,
    const uint2* __restrict__ KP2, const uint2* __restrict__ VP,
    uint4* __restrict__ OQ)
{
    extern __shared__ uint32_t sm[];
    const uint32_t smBase = (uint32_t)__cvta_generic_to_shared(sm);
    uint32_t* ps = sm + 18432;
    float*    l2 = (float*)(sm + 23040);

    const int qb = (gridDim.x - 1) - blockIdx.x;
    const int h = blockIdx.y, hk = h >> 3;
    const int tid = threadIdx.x, lane = tid & 31, w = tid >> 5;
    const int wm = w >> 1, wn = w & 1;
    const int gid = lane >> 2, tig = lane & 3;

    // Q fragments: 2 m-tiles (rows wm*32 + mt*16)
    uint32_t qh[8][2][4];
#pragma unroll
    for (int c = 0; c < 8; c++)
#pragma unroll
        for (int mt = 0; mt < 2; mt++) {
            size_t i0 = (size_t)(qb * 128 + wm * 32 + mt * 16 + gid) * 2048
                      + h * 64 + c * 8 + tig;
            qh[c][mt][0] = Qh[i0];     qh[c][mt][1] = Qh[i0 + 8 * 2048];
            qh[c][mt][2] = Qh[i0 + 4]; qh[c][mt][3] = Qh[i0 + 8 * 2048 + 4];
        }

#define FL_ISSUE(kb, buf) do {                                                 \
    _Pragma("unroll")                                                          \
    for (int l = 0; l < 4; l++) {                                              \
        int task = tid + l * 256;                                              \
        int cc = task >> 7, ss = (task >> 1) & 63, hf = task & 1;              \
        cp16(smBase + ((buf) * 4096 + (cc * 64 + ss) * 8 + hf * 4) * 4,        \
             KP2 + ((size_t)(hk * 8 + cc) * SEQ + (kb) * 64 + ss) * 4 + hf * 2); \
    }                                                                          \
    _Pragma("unroll")                                                          \
    for (int l = 0; l < 4; l++) {                                              \
        int task = tid + l * 256;                                              \
        int dd = task >> 3, jj = (task >> 1) & 3, hf = task & 1;               \
        cp16(smBase + (8192 + (buf) * 5120 + (dd * 20 + jj * 4 + hf * 2) * 2) * 4, \
             VP + ((size_t)(hk * 128 + dd) * 256 + (kb) * 4 + jj) * 4 + hf * 2); \
    }                                                                          \
    cp_commit();                                                               \
} while (0)

    float l_[2][2] = { {0.f, 0.f}, {0.f, 0.f} };
    float o[2][8][4];
#pragma unroll
    for (int mt = 0; mt < 2; mt++)
#pragma unroll
        for (int nt = 0; nt < 8; nt++)
#pragma unroll
            for (int q = 0; q < 4; q++) o[mt][nt][q] = 0.f;

    const int kbmax = 2 * qb + 1;
    FL_ISSUE(0, 0);

    for (int kb = 0; kb <= kbmax; kb++) {
        __syncthreads();                       // prior PV done (buffers + P free)
        if (kb < kbmax) { FL_ISSUE(kb + 1, (kb + 1) & 1); cp_wait1(); }
        else             cp_wait0();
        __syncthreads();                       // buf[kb] ready

        const int buf = kb & 1;
        const uint2* Ksp = (const uint2*)sm + buf * 2048;
        const uint2* Vsp = (const uint2*)(sm + 8192) + buf * 2560;

        // QK: warp 32 rows x 32 cols; each K frag feeds 2 mma
        float s[2][4][4];
#pragma unroll
        for (int mt = 0; mt < 2; mt++)
#pragma unroll
            for (int nt = 0; nt < 4; nt++)
#pragma unroll
                for (int q = 0; q < 4; q++) s[mt][nt][q] = 0.f;
#pragma unroll
        for (int c = 0; c < 8; c++) {
            const uint2* kbp = Ksp + c * 256 + tig;
#pragma unroll
            for (int nt = 0; nt < 4; nt++) {
                uint2 kf = kbp[((wn * 4 + nt) * 8 + gid) * 4];
                uint32_t b[2] = { kf.x, kf.y };
                mma16h(s[0][nt], qh[c][0], b);
                mma16h(s[1][nt], qh[c][1], b);
            }
        }

        // causal mask (near-diagonal tiles)
        if (kb >= 2 * qb) {
#pragma unroll
            for (int mt = 0; mt < 2; mt++) {
                int row = qb * 128 + wm * 32 + mt * 16 + gid;
#pragma unroll
                for (int nt = 0; nt < 4; nt++) {
                    int col = kb * 64 + wn * 32 + nt * 8 + 2 * tig;
                    if (col     > row)     s[mt][nt][0] = -1e30f;
                    if (col + 1 > row)     s[mt][nt][1] = -1e30f;
                    if (col     > row + 8) s[mt][nt][2] = -1e30f;
                    if (col + 1 > row + 8) s[mt][nt][3] = -1e30f;
                }
            }
        }

        // exp + P store (pitch-36 u32 pairs) + partial row sums
#pragma unroll
        for (int mt = 0; mt < 2; mt++) {
            float rs0 = 0.f, rs1 = 0.f;
            const int r = wm * 32 + mt * 16 + gid;
#pragma unroll
            for (int nt = 0; nt < 4; nt++) {
                float e0 = __expf(s[mt][nt][0]), e1 = __expf(s[mt][nt][1]);
                float e2 = __expf(s[mt][nt][2]), e3 = __expf(s[mt][nt][3]);
                rs0 += e0 + e1; rs1 += e2 + e3;
                int cp = wn * 16 + nt * 4 + tig;
                ps[r * 36 + cp]       = h2pack(e0, e1);
                ps[(r + 8) * 36 + cp] = h2pack(e2, e3);
            }
            rs0 += __shfl_xor_sync(0xffffffffu, rs0, 1);
            rs0 += __shfl_xor_sync(0xffffffffu, rs0, 2);
            rs1 += __shfl_xor_sync(0xffffffffu, rs1, 1);
            rs1 += __shfl_xor_sync(0xffffffffu, rs1, 2);
            l_[mt][0] += rs0; l_[mt][1] += rs1;
        }
        __syncthreads();                       // P visible to sibling warps

        // PV: warp 32 rows x 64 d cols; each V frag feeds 2 mma
#pragma unroll
        for (int j = 0; j < 4; j++) {
            uint32_t aP[2][4];
#pragma unroll
            for (int mt = 0; mt < 2; mt++) {
                const int r = wm * 32 + mt * 16 + gid;
                aP[mt][0] = ps[r * 36 + j * 8 + tig];
                aP[mt][1] = ps[(r + 8) * 36 + j * 8 + tig];
                aP[mt][2] = ps[r * 36 + j * 8 + tig + 4];
                aP[mt][3] = ps[(r + 8) * 36 + j * 8 + tig + 4];
            }
#pragma unroll
            for (int nt = 0; nt < 8; nt++) {
                uint2 vv = Vsp[(wn * 64 + nt * 8 + gid) * 20 + j * 4 + tig];
                uint32_t b[2] = { vv.x, vv.y };
                mma16h(o[0][nt], aP[0], b);
                mma16h(o[1][nt], aP[1], b);
            }
        }
    }

    // combine cross-warp l partials
    __syncthreads();
    if (tig == 0) {
#pragma unroll
        for (int mt = 0; mt < 2; mt++) {
            int r = wm * 32 + mt * 16 + gid;
            l2[wn * 128 + r]     = l_[mt][0];
            l2[wn * 128 + r + 8] = l_[mt][1];
        }
    }
    __syncthreads();

    // epilogue: normalize, store fp16 a-frag quads
#pragma unroll
    for (int mt = 0; mt < 2; mt++) {
        const int r = wm * 32 + mt * 16 + gid;
        const float il0 = 1.0f / (l2[r] + l2[128 + r]);
        const float il1 = 1.0f / (l2[r + 8] + l2[128 + r + 8]);
        const int rgO = qb * 8 + wm * 2 + mt;
#pragma unroll
        for (int jj = 0; jj < 4; jj++) {
            int c = h * 8 + wn * 4 + jj;
            uint4 u;
            u.x = h2pack(o[mt][2*jj][0]   * il0, o[mt][2*jj][1]   * il0);
            u.y = h2pack(o[mt][2*jj][2]   * il1, o[mt][2*jj][3]   * il1);
            u.z = h2pack(o[mt][2*jj+1][0] * il0, o[mt][2*jj+1][1] * il0);
            u.w = h2pack(o[mt][2*jj+1][2] * il1, o[mt][2*jj+1][3] * il1);
            OQ[((size_t)(c * 256 + rgO) * 8 + gid) * 4 + tig] = u;
        }
    }
}

// ---------------- launch ----------------
extern "C" void kernel_launch(void* const* d_in, const int* in_sizes, int n_in,
                              void* d_out, int out_size)
{
    const float* X  = (const float*)d_in[0];
    const float* Wq = (const float*)d_in[1];
    const float* Wk = (const float*)d_in[2];
    const float* Wv = (const float*)d_in[3];
    const float* Wo = (const float*)d_in[4];
    const int*  pos = (const int*)d_in[5];
    float* out = (float*)d_out;

    uint4 *XhQ, *OQp;
    uint2 *WqB, *WkB, *WvB, *WoB, *KP2p, *VPp;
    uint32_t *Qhp;
    cudaGetSymbolAddress((void**)&XhQ,  g_XhQ);
    cudaGetSymbolAddress((void**)&WqB,  g_WqB);
    cudaGetSymbolAddress((void**)&WkB,  g_WkB);
    cudaGetSymbolAddress((void**)&WvB,  g_WvB);
    cudaGetSymbolAddress((void**)&WoB,  g_WoB);
    cudaGetSymbolAddress((void**)&Qhp,  g_Qh);
    cudaGetSymbolAddress((void**)&KP2p, g_KP2);
    cudaGetSymbolAddress((void**)&VPp,  g_VP);
    cudaGetSymbolAddress((void**)&OQp,  g_OQ);

    cudaFuncSetAttribute(gemm_f16q<0>, cudaFuncAttributeMaxDynamicSharedMemorySize, F16Q_SMEM_BYTES);
    cudaFuncSetAttribute(gemm_f16q<1>, cudaFuncAttributeMaxDynamicSharedMemorySize, F16Q_SMEM_BYTES);
    cudaFuncSetAttribute(gemm_f16q<2>, cudaFuncAttributeMaxDynamicSharedMemorySize, F16Q_SMEM_BYTES);
    cudaFuncSetAttribute(gemm_f16q<3>, cudaFuncAttributeMaxDynamicSharedMemorySize, F16Q_SMEM_BYTES);
    cudaFuncSetAttribute(flash_mma, cudaFuncAttributeMaxDynamicSharedMemorySize, FL_SMEM_BYTES);

    // prep
    prep_XQh<<<(HID/16) * (SEQ/16) * 32 / 256, 256>>>(X, XhQ);
    prep_W2<<<(HID/16) * DQTOT * 4 / 256, 256>>>(Wq, WqB, DQTOT, DQTOT - 1, 12);
    prep_W2<<<(HID/16) * DKVTOT * 4 / 256, 256>>>(Wk, WkB, DKVTOT, DKVTOT - 1, 9);
    prep_W2<<<(HID/16) * DKVTOT * 4 / 256, 256>>>(Wv, WvB, DKVTOT, DKVTOT - 1, 9);
    prep_W2<<<(DQTOT/16) * HID * 4 / 256, 256>>>(Wo, WoB, HID, HID - 1, 11);

    // projections (fp16) with fused RoPE
    gemm_f16q<1><<<dim3(NHQ, SEQ / 128), 256, F16Q_SMEM_BYTES>>>(
        XhQ, WqB, pos, nullptr, nullptr, Qhp, nullptr, SEQ, DQTOT, HID);
    gemm_f16q<2><<<dim3(NHKV, SEQ / 128), 256, F16Q_SMEM_BYTES>>>(
        XhQ, WkB, pos, nullptr, nullptr, nullptr, KP2p, SEQ, DKVTOT, HID);
    gemm_f16q<3><<<dim3(DKVTOT / 128, SEQ / 128), 256, F16Q_SMEM_BYTES>>>(
        XhQ, WvB, nullptr, nullptr, VPp, nullptr, nullptr, SEQ, DKVTOT, HID);

    // attention
    flash_mma<<<dim3(SEQ / 128, NHQ), 256, FL_SMEM_BYTES>>>(Qhp, KP2p, VPp, OQp);

    // output projection
    gemm_f16q<0><<<dim3(HID / 128, SEQ / 128), 256, F16Q_SMEM_BYTES>>>(
        OQp, WoB, nullptr, out, nullptr, nullptr, nullptr, SEQ, HID, DQTOT);
}

// round 17
// speedup vs baseline: 1.0588x; 1.0588x over previous
#include <cuda_runtime.h>
#include <cuda_fp16.h>
#include <math.h>
#include <stdint.h>

#define SEQ   4096
#define HID   2048
#define NHQ   32
#define NHKV  4
#define DH    128
#define DQTOT (NHQ*DH)
#define DKVTOT (NHKV*DH)

// ---------------- scratch ----------------
__device__ uint4 g_XhQ [(HID/16) * (SEQ/16) * 32];   // X fp16 a-frag quads, 16MB
__device__ uint2 g_WqB[(HID/16) * DQTOT * 4];        // Wq fp16 b-frag pairs, 16MB
__device__ uint2 g_WkB[(HID/16) * DKVTOT * 4];       // 2MB
__device__ uint2 g_WvB[(HID/16) * DKVTOT * 4];       // 2MB
__device__ uint2 g_WoB[(DQTOT/16) * HID * 4];        // 16MB
__device__ uint32_t g_Qh[SEQ * DQTOT / 2];           // Q fp16 pairs row-major, 32MB
__device__ uint2 g_KP2[NHKV * 8 * SEQ * 4];          // K fp16 b-frag layout, 4MB
__device__ uint2 g_VP[NHKV * DH * (SEQ/16) * 4];     // V fp16 pair layout, 4MB
__device__ uint4 g_OQ[(DQTOT/16) * (SEQ/16) * 32];   // O fp16 a-frag quads, 32MB

// ---------------- helpers ----------------
__device__ __forceinline__ uint32_t h2pack(float a, float b) {
    __half2 h = __floats2half2_rn(a, b);
    return *(uint32_t*)&h;
}
__device__ __forceinline__ void mma16h(float* c, const uint32_t* a, const uint32_t* b) {
    asm volatile("mma.sync.aligned.m16n8k16.row.col.f32.f16.f16.f32 "
        "{%0,%1,%2,%3}, {%4,%5,%6,%7}, {%8,%9}, {%0,%1,%2,%3};\n"
        : "+f"(c[0]), "+f"(c[1]), "+f"(c[2]), "+f"(c[3])
        : "r"(a[0]), "r"(a[1]), "r"(a[2]), "r"(a[3]), "r"(b[0]), "r"(b[1]));
}
__device__ __forceinline__ void cp16(uint32_t dst, const void* src) {
    asm volatile("cp.async.ca.shared.global [%0], [%1], 16;\n" :: "r"(dst), "l"(src));
}
__device__ __forceinline__ void cp_commit() { asm volatile("cp.async.commit_group;\n"); }
__device__ __forceinline__ void cp_wait0()  { asm volatile("cp.async.wait_group 0;\n"); }
__device__ __forceinline__ void cp_wait1()  { asm volatile("cp.async.wait_group 1;\n"); }

// ---------------- prep kernels ----------------
__global__ void prep_XQh(const float* __restrict__ X, uint4* __restrict__ XhQ)
{
    int id  = blockIdx.x * 256 + threadIdx.x;
    int tig = id & 3, gid = (id >> 2) & 7, rg = (id >> 5) & (SEQ/16 - 1), c = id >> 13;
    const float* p0 = X + (size_t)(rg * 16 + gid) * HID + c * 16 + 2 * tig;
    const float* p1 = p0 + (size_t)8 * HID;
    float2 a0 = *(const float2*)p0, a1 = *(const float2*)p1;
    float2 a2 = *(const float2*)(p0 + 8), a3 = *(const float2*)(p1 + 8);
    XhQ[id] = make_uint4(h2pack(a0.x, a0.y), h2pack(a1.x, a1.y),
                         h2pack(a2.x, a2.y), h2pack(a3.x, a3.y));
}
__global__ void prep_W2(const float* __restrict__ W, uint2* __restrict__ out,
                        int N, int nMask, int nShift)
{
    int id = blockIdx.x * 256 + threadIdx.x;
    int tg = id & 3, n = (id >> 2) & nMask, c = id >> (2 + nShift);
    const float* Wp = W + (size_t)(16 * c + 2 * tg) * N + n;
    out[id] = make_uint2(h2pack(Wp[0],           Wp[(size_t)N]),
                         h2pack(Wp[(size_t)8*N], Wp[(size_t)9*N]));
}

// ===========================================================================
// gemm_f16q<EPI>: fp16 single-pass GEMM (unchanged from R14).
// EPI=0: f32 C (Wo). 1: RoPE-Q -> Qh. 2: RoPE-K -> KP2. 3: V pack -> VP.
// ===========================================================================
#define F16Q_SMEM_BYTES 67584

template<int EPI>
__global__ __launch_bounds__(256, 2) void gemm_f16q(
    const uint4* __restrict__ AQ, const uint2* __restrict__ B2,
    const int* __restrict__ pos, float* __restrict__ C,
    uint2* __restrict__ VP, uint32_t* __restrict__ Qh, uint2* __restrict__ KP2,
    int M, int N, int K)
{
    extern __shared__ uint32_t smq[];
    const uint32_t smBase = (uint32_t)__cvta_generic_to_shared(smq);
    const int tid = threadIdx.x, lane = tid & 31, w = tid >> 5;
    const int wm = w >> 2, wn = w & 3;
    const int m0 = blockIdx.y * 128, n0 = blockIdx.x * 128;
    const int hb = blockIdx.x;
    const int gid = lane >> 2, tig = lane & 3;
    const int Mg = M >> 4, rg0 = m0 >> 4;

    float c[4][4][4];
#pragma unroll
    for (int mt = 0; mt < 4; mt++)
#pragma unroll
        for (int nt = 0; nt < 4; nt++)
#pragma unroll
            for (int q = 0; q < 4; q++) c[mt][nt][q] = 0.f;

#define F16Q_LOAD(t, buf) do {                                                 \
    _Pragma("unroll")                                                          \
    for (int l = 0; l < 2; l++) {                                              \
        int task = tid + l * 256;                                              \
        int ck = task >> 8, rg = (task >> 5) & 7, ln = task & 31;              \
        cp16(smBase + ((buf) * 512 + ck * 256 + rg * 32 + ln) * 16,            \
             AQ + ((size_t)((t) * 2 + ck) * Mg + rg0 + rg) * 32 + ln);         \
    }                                                                          \
    _Pragma("unroll")                                                          \
    for (int l = 0; l < 2; l++) {                                              \
        int task = tid + l * 256;                                              \
        int ck = task >> 8, n = (task >> 1) & 127, hf = task & 1;              \
        cp16(smBase + 16384 + ((buf) * 1024 + (ck * 128 + n) * 4 + hf * 2) * 8,\
             B2 + ((size_t)((t) * 2 + ck) * N + n0 + n) * 4 + hf * 2);         \
    }                                                                          \
    cp_commit();                                                               \
} while (0)

    const uint4* AQS = (const uint4*)smq;
    const uint2* B2S = (const uint2*)(smq + 4096);
    const int NT = K / 32;
    F16Q_LOAD(0, 0);
    for (int t = 0; t < NT; t++) {
        cp_wait0();
        __syncthreads();
        if (t + 1 < NT) F16Q_LOAD(t + 1, (t + 1) & 1);
        const int buf = t & 1;
#pragma unroll
        for (int ck = 0; ck < 2; ck++) {
            uint32_t a[4][4];
#pragma unroll
            for (int mt = 0; mt < 4; mt++) {
                uint4 va = AQS[buf * 512 + ck * 256 + (wm * 4 + mt) * 32 + lane];
                a[mt][0] = va.x; a[mt][1] = va.y; a[mt][2] = va.z; a[mt][3] = va.w;
            }
#pragma unroll
            for (int nt = 0; nt < 4; nt++) {
                int nc = wn * 32 + nt * 8 + gid;
                uint2 bu = B2S[buf * 1024 + ck * 512 + nc * 4 + tig];
                uint32_t b[2] = { bu.x, bu.y };
#pragma unroll
                for (int mt = 0; mt < 4; mt++)
                    mma16h(c[mt][nt], a[mt], b);
            }
        }
    }

    if (EPI == 0) {
#pragma unroll
        for (int mt = 0; mt < 4; mt++)
#pragma unroll
            for (int nt = 0; nt < 4; nt++) {
                int row = m0 + wm * 64 + mt * 16 + gid;
                int col = n0 + wn * 32 + nt * 8 + 2 * tig;
                *(float2*)&C[(size_t)row * N + col] = make_float2(c[mt][nt][0], c[mt][nt][1]);
                *(float2*)&C[(size_t)(row + 8) * N + col] = make_float2(c[mt][nt][2], c[mt][nt][3]);
            }
        return;
    }
    if (EPI == 3) {
        __syncthreads();
        uint32_t* stg = smq;
#pragma unroll
        for (int mt = 0; mt < 4; mt++)
#pragma unroll
            for (int nt = 0; nt < 4; nt++) {
                int rm = wm * 64 + mt * 16 + gid;
                int cu = wn * 16 + nt * 4 + tig;
                stg[rm * 66 + cu]       = h2pack(c[mt][nt][0], c[mt][nt][1]);
                stg[(rm + 8) * 66 + cu] = h2pack(c[mt][nt][2], c[mt][nt][3]);
            }
        __syncthreads();
        const __half* sh = (const __half*)smq;
        int hk = n0 >> 7, jg0 = m0 >> 4;
#pragma unroll
        for (int i = 0; i < 16; i++) {
            int task = tid + i * 256;
            int d = task >> 5, jl = (task >> 2) & 7, tg = task & 3;
            int s = 16 * jl + 2 * tg;
            __half2 pA = __halves2half2(sh[s * 132 + d],       sh[(s + 1) * 132 + d]);
            __half2 pB = __halves2half2(sh[(s + 8) * 132 + d], sh[(s + 9) * 132 + d]);
            VP[((size_t)(hk * 128 + d) * 256 + jg0 + jl) * 4 + tg] =
                make_uint2(*(uint32_t*)&pA, *(uint32_t*)&pB);
        }
        return;
    }
    __syncthreads();
    float* stage = (float*)smq;   // [128][132]
#pragma unroll
    for (int mt = 0; mt < 4; mt++)
#pragma unroll
        for (int nt = 0; nt < 4; nt++) {
            int row = wm * 64 + mt * 16 + gid;
            int col = wn * 32 + nt * 8 + 2 * tig;
            *(float2*)&stage[row * 132 + col] = make_float2(c[mt][nt][0], c[mt][nt][1]);
            *(float2*)&stage[(row + 8) * 132 + col] = make_float2(c[mt][nt][2], c[mt][nt][3]);
        }
    __syncthreads();
    {
        const int j  = tid & 31;
        const int rb = tid >> 5;
        const float inv0 = powf(10000.0f, -(float)(2 * j)     / 64.0f);
        const float inv1 = powf(10000.0f, -(float)(2 * j + 1) / 64.0f);
        const float SC = (EPI == 1) ? 0.08838834764831845f : 1.0f;
        const int cL = j >> 3, tg = j & 3, slot = (j >> 2) & 1;
#pragma unroll 4
        for (int i = 0; i < 16; i++) {
            int r = rb + i * 8;
            int s = m0 + r;
            float p = (float)pos[s];
            float s0, c0, s1, c1;
            sincosf(p * inv0, &s0, &c0);
            sincosf(p * inv1, &s1, &c1);
            float xL0 = stage[r * 132 + 2 * j],      xL1 = stage[r * 132 + 2 * j + 1];
            float xH0 = stage[r * 132 + 2 * j + 64], xH1 = stage[r * 132 + 2 * j + 65];
            float oL0 = (xL0 * c0 - xH0 * s0) * SC;
            float oL1 = (xL1 * c1 - xH1 * s1) * SC;
            float oH0 = (xH0 * c0 + xL0 * s0) * SC;
            float oH1 = (xH1 * c1 + xL1 * s1) * SC;
            if (EPI == 1) {
                size_t base = (size_t)s * 2048 + hb * 64;
                Qh[base + j]      = h2pack(oL0, oL1);
                Qh[base + 32 + j] = h2pack(oH0, oH1);
            } else {
                ((uint32_t*)&KP2[((size_t)(hb * 8 + cL) * SEQ + s) * 4 + tg])[slot] =
                    h2pack(oL0, oL1);
                ((uint32_t*)&KP2[((size_t)(hb * 8 + 4 + cL) * SEQ + s) * 4 + tg])[slot] =
                    h2pack(oH0, oH1);
            }
        }
    }
}

// ===========================================================================
// flash_mma (R14 math, smaller CTA): 64 q-rows, 128 threads (4 warps of 16
// rows), 64-wide kv tiles. P register-resident (S C-frag == PV A-frag).
// Per-CTA smem 72KB -> 2-3 CTAs/SM with independent barriers, overlapping
// one CTA's exp/barrier phase with another's mma phase.
// smem u32: K uint2[2][2048] @0, V uint2[2][2560] @8192.
// ===========================================================================
#define FL_SMEM_BYTES (18432 * 4)   // 73728

__global__ __launch_bounds__(128, 2) void flash_mma(
    const uint32_t* __restrict__ Qh,
    const uint2* __restrict__ KP2, const uint2* __restrict__ VP,
    uint4* __restrict__ OQ)
{
    extern __shared__ uint32_t sm[];
    const uint32_t smBase = (uint32_t)__cvta_generic_to_shared(sm);
    const int qb = (gridDim.x - 1) - blockIdx.x;   // heavy blocks first
    const int h = blockIdx.y, hk = h >> 3;
    const int tid = threadIdx.x, lane = tid & 31, w = tid >> 5;
    const int gid = lane >> 2, tig = lane & 3;
    const int r0 = w * 16 + gid, r0g = qb * 64 + r0;

    // Q fragments: fp16 pairs, row pitch 2048 u32
    uint32_t qh[8][4];
#pragma unroll
    for (int c = 0; c < 8; c++) {
        size_t i0 = (size_t)r0g * 2048 + h * 64 + c * 8 + tig;
        qh[c][0] = Qh[i0];     qh[c][1] = Qh[i0 + 8 * 2048];
        qh[c][2] = Qh[i0 + 4]; qh[c][3] = Qh[i0 + 8 * 2048 + 4];
    }

#define FL_ISSUE(kb, buf) do {                                                 \
    _Pragma("unroll")                                                          \
    for (int l = 0; l < 8; l++) {                                              \
        int task = tid + l * 128;                                              \
        int cc = task >> 7, ss = (task >> 1) & 63, hf = task & 1;              \
        cp16(smBase + ((buf) * 4096 + (cc * 64 + ss) * 8 + hf * 4) * 4,        \
             KP2 + ((size_t)(hk * 8 + cc) * SEQ + (kb) * 64 + ss) * 4 + hf * 2); \
    }                                                                          \
    _Pragma("unroll")                                                          \
    for (int l = 0; l < 8; l++) {                                              \
        int task = tid + l * 128;                                              \
        int dd = task >> 3, jj = (task >> 1) & 3, hf = task & 1;               \
        cp16(smBase + (8192 + (buf) * 5120 + (dd * 20 + jj * 4 + hf * 2) * 2) * 4, \
             VP + ((size_t)(hk * 128 + dd) * 256 + (kb) * 4 + jj) * 4 + hf * 2); \
    }                                                                          \
    cp_commit();                                                               \
} while (0)

    float l_[2] = { 0.f, 0.f };
    float o[16][4];
#pragma unroll
    for (int nt = 0; nt < 16; nt++)
#pragma unroll
        for (int q = 0; q < 4; q++) o[nt][q] = 0.f;

    const int kbmax = qb;
    FL_ISSUE(0, 0);

    for (int kb = 0; kb <= kbmax; kb++) {
        __syncthreads();
        if (kb < kbmax) { FL_ISSUE(kb + 1, (kb + 1) & 1); cp_wait1(); }
        else             cp_wait0();
        __syncthreads();

        const int buf = kb & 1;
        const uint2* Ksp = (const uint2*)sm + buf * 2048;
        const uint2* Vsp = (const uint2*)(sm + 8192) + buf * 2560;

        // S = Q K^T (fp16): 8 chunks x 8 n-tiles
        float s[8][4];
#pragma unroll
        for (int nt = 0; nt < 8; nt++)
#pragma unroll
            for (int q = 0; q < 4; q++) s[nt][q] = 0.f;
#pragma unroll
        for (int c = 0; c < 8; c++) {
            const uint2* kbp = Ksp + c * 256 + tig;
#pragma unroll
            for (int nt = 0; nt < 8; nt++) {
                uint2 kf = kbp[(nt * 8 + gid) * 4];
                uint32_t b[2] = { kf.x, kf.y };
                mma16h(s[nt], qh[c], b);
            }
        }
        if (kb >= qb) {   // diagonal tile
#pragma unroll
            for (int nt = 0; nt < 8; nt++) {
                int col = kb * 64 + nt * 8 + 2 * tig;
                if (col     > r0g)     s[nt][0] = -1e30f;
                if (col + 1 > r0g)     s[nt][1] = -1e30f;
                if (col     > r0g + 8) s[nt][2] = -1e30f;
                if (col + 1 > r0g + 8) s[nt][3] = -1e30f;
            }
        }
        float rs0 = 0.f, rs1 = 0.f;
        uint32_t pa[4][4];
#pragma unroll
        for (int j = 0; j < 4; j++) {
            float e00 = __expf(s[2*j][0]),   e01 = __expf(s[2*j][1]);
            float e02 = __expf(s[2*j][2]),   e03 = __expf(s[2*j][3]);
            float e10 = __expf(s[2*j+1][0]), e11 = __expf(s[2*j+1][1]);
            float e12 = __expf(s[2*j+1][2]), e13 = __expf(s[2*j+1][3]);
            rs0 += (e00 + e01) + (e10 + e11);
            rs1 += (e02 + e03) + (e12 + e13);
            pa[j][0] = h2pack(e00, e01); pa[j][1] = h2pack(e02, e03);
            pa[j][2] = h2pack(e10, e11); pa[j][3] = h2pack(e12, e13);
        }
        rs0 += __shfl_xor_sync(0xffffffffu, rs0, 1);
        rs0 += __shfl_xor_sync(0xffffffffu, rs0, 2);
        rs1 += __shfl_xor_sync(0xffffffffu, rs1, 1);
        rs1 += __shfl_xor_sync(0xffffffffu, rs1, 2);
        l_[0] += rs0; l_[1] += rs1;
#pragma unroll
        for (int j = 0; j < 4; j++) {
#pragma unroll
            for (int nt = 0; nt < 16; nt++) {
                uint2 vv = Vsp[(nt * 8 + gid) * 20 + j * 4 + tig];
                uint32_t b[2] = { vv.x, vv.y };
                mma16h(o[nt], pa[j], b);
            }
        }
    }
    {
        const float il0 = 1.0f / l_[0], il1 = 1.0f / l_[1];
        const int rgO = qb * 4 + w;
#pragma unroll
        for (int j = 0; j < 8; j++) {
            int c = h * 8 + j;
            uint4 u;
            u.x = h2pack(o[2*j][0]   * il0, o[2*j][1]   * il0);
            u.y = h2pack(o[2*j][2]   * il1, o[2*j][3]   * il1);
            u.z = h2pack(o[2*j+1][0] * il0, o[2*j+1][1] * il0);
            u.w = h2pack(o[2*j+1][2] * il1, o[2*j+1][3] * il1);
            OQ[((size_t)(c * 256 + rgO) * 8 + gid) * 4 + tig] = u;
        }
    }
}

// ---------------- launch ----------------
extern "C" void kernel_launch(void* const* d_in, const int* in_sizes, int n_in,
                              void* d_out, int out_size)
{
    const float* X  = (const float*)d_in[0];
    const float* Wq = (const float*)d_in[1];
    const float* Wk = (const float*)d_in[2];
    const float* Wv = (const float*)d_in[3];
    const float* Wo = (const float*)d_in[4];
    const int*  pos = (const int*)d_in[5];
    float* out = (float*)d_out;

    uint4 *XhQ, *OQp;
    uint2 *WqB, *WkB, *WvB, *WoB, *KP2p, *VPp;
    uint32_t *Qhp;
    cudaGetSymbolAddress((void**)&XhQ,  g_XhQ);
    cudaGetSymbolAddress((void**)&WqB,  g_WqB);
    cudaGetSymbolAddress((void**)&WkB,  g_WkB);
    cudaGetSymbolAddress((void**)&WvB,  g_WvB);
    cudaGetSymbolAddress((void**)&WoB,  g_WoB);
    cudaGetSymbolAddress((void**)&Qhp,  g_Qh);
    cudaGetSymbolAddress((void**)&KP2p, g_KP2);
    cudaGetSymbolAddress((void**)&VPp,  g_VP);
    cudaGetSymbolAddress((void**)&OQp,  g_OQ);

    cudaFuncSetAttribute(gemm_f16q<0>, cudaFuncAttributeMaxDynamicSharedMemorySize, F16Q_SMEM_BYTES);
    cudaFuncSetAttribute(gemm_f16q<1>, cudaFuncAttributeMaxDynamicSharedMemorySize, F16Q_SMEM_BYTES);
    cudaFuncSetAttribute(gemm_f16q<2>, cudaFuncAttributeMaxDynamicSharedMemorySize, F16Q_SMEM_BYTES);
    cudaFuncSetAttribute(gemm_f16q<3>, cudaFuncAttributeMaxDynamicSharedMemorySize, F16Q_SMEM_BYTES);
    cudaFuncSetAttribute(flash_mma, cudaFuncAttributeMaxDynamicSharedMemorySize, FL_SMEM_BYTES);

    // prep
    prep_XQh<<<(HID/16) * (SEQ/16) * 32 / 256, 256>>>(X, XhQ);
    prep_W2<<<(HID/16) * DQTOT * 4 / 256, 256>>>(Wq, WqB, DQTOT, DQTOT - 1, 12);
    prep_W2<<<(HID/16) * DKVTOT * 4 / 256, 256>>>(Wk, WkB, DKVTOT, DKVTOT - 1, 9);
    prep_W2<<<(HID/16) * DKVTOT * 4 / 256, 256>>>(Wv, WvB, DKVTOT, DKVTOT - 1, 9);
    prep_W2<<<(DQTOT/16) * HID * 4 / 256, 256>>>(Wo, WoB, HID, HID - 1, 11);

    // projections (fp16) with fused RoPE
    gemm_f16q<1><<<dim3(NHQ, SEQ / 128), 256, F16Q_SMEM_BYTES>>>(
        XhQ, WqB, pos, nullptr, nullptr, Qhp, nullptr, SEQ, DQTOT, HID);
    gemm_f16q<2><<<dim3(NHKV, SEQ / 128), 256, F16Q_SMEM_BYTES>>>(
        XhQ, WkB, pos, nullptr, nullptr, nullptr, KP2p, SEQ, DKVTOT, HID);
    gemm_f16q<3><<<dim3(DKVTOT / 128, SEQ / 128), 256, F16Q_SMEM_BYTES>>>(
        XhQ, WvB, nullptr, nullptr, VPp, nullptr, nullptr, SEQ, DKVTOT, HID);

    // attention (64-row CTAs, 2-3 per SM)
    flash_mma<<<dim3(SEQ / 64, NHQ), 128, FL_SMEM_BYTES>>>(Qhp, KP2p, VPp, OQp);

    // output projection
    gemm_f16q<0><<<dim3(HID / 128, SEQ / 128), 256, F16Q_SMEM_BYTES>>>(
        OQp, WoB, nullptr, out, nullptr, nullptr, nullptr, SEQ, HID, DQTOT);
}